// round 2
// baseline (speedup 1.0000x reference)
#include <cuda_runtime.h>
#include <math.h>

// Problem constants
#define LL   1024
#define DMM  128
#define HH   4
#define DH_  32
#define QP_  4
#define VP_  4
#define DP_  64

// Scratch (static device globals; allocation-free)
__device__ float g_Ahat[LL * HH * 44];   // [Q*scale, w*Qg] per (i,h)
__device__ float g_Bhat[LL * HH * 44];   // [K, Kg]        per (j,h)
__device__ float g_ci[HH * LL];          // -0.5*w*|Qg|^2
__device__ float g_cj[HH * LL];          // -0.5*w*|Kg|^2
__device__ float g_V [LL * 128];         // V[i][h*32+d]
__device__ float g_Vg[LL * 48];          // Vg[i][h*12+k]
__device__ float g_attn[(size_t)HH * LL * LL]; // attn[h][i][j]
__device__ float g_os  [LL * 128];       // o_s
__device__ float g_optg[LL * 48];        // o_pt_g
__device__ float g_opair[LL * 256];      // o_pair

// ---------------------------------------------------------------------------
// Kernel P: layernorm + all projections + frame transforms. grid=128, blk=128
// Each block processes 8 rows.
// ---------------------------------------------------------------------------
__global__ __launch_bounds__(128) void kprep(
    const float* __restrict__ single, const float* __restrict__ T,
    const float* __restrict__ w_C,    const float* __restrict__ ln_g,
    const float* __restrict__ ln_b,
    const float* __restrict__ Wq, const float* __restrict__ Wk,
    const float* __restrict__ Wv, const float* __restrict__ Wqpt,
    const float* __restrict__ Wkpt, const float* __restrict__ Wvpt)
{
    __shared__ float zs[8][128];
    __shared__ float proj[8][528];
    __shared__ float red[2][4];

    const int tid = threadIdx.x;
    const int i0  = blockIdx.x * 8;
    const int lane = tid & 31, wid = tid >> 5;

    // Layernorm per row
    for (int r = 0; r < 8; r++) {
        float x = single[(i0 + r) * 128 + tid];
        float s = x, s2 = x * x;
        #pragma unroll
        for (int o = 16; o; o >>= 1) {
            s  += __shfl_xor_sync(0xffffffffu, s,  o);
            s2 += __shfl_xor_sync(0xffffffffu, s2, o);
        }
        if (lane == 0) { red[0][wid] = s; red[1][wid] = s2; }
        __syncthreads();
        float sum  = red[0][0] + red[0][1] + red[0][2] + red[0][3];
        float sum2 = red[1][0] + red[1][1] + red[1][2] + red[1][3];
        float mu  = sum * (1.f / 128.f);
        float var = sum2 * (1.f / 128.f) - mu * mu;
        float inv = rsqrtf(var + 1e-5f);
        zs[r][tid] = (x - mu) * inv * ln_g[tid] + ln_b[tid];
        __syncthreads();
    }

    // Projections: 528 outputs per row. proj layout: Q 0, K 128, V 256,
    // Qpt 384, Kpt 432, Vpt 480.
    for (int o = tid; o < 528; o += 128) {
        const float* W; int col, ow;
        if      (o < 128) { W = Wq;   col = o;       ow = 128; }
        else if (o < 256) { W = Wk;   col = o - 128; ow = 128; }
        else if (o < 384) { W = Wv;   col = o - 256; ow = 128; }
        else if (o < 432) { W = Wqpt; col = o - 384; ow = 48;  }
        else if (o < 480) { W = Wkpt; col = o - 432; ow = 48;  }
        else              { W = Wvpt; col = o - 480; ow = 48;  }
        float acc[8] = {0,0,0,0,0,0,0,0};
        for (int d = 0; d < 128; d++) {
            float w = W[d * ow + col];
            #pragma unroll
            for (int r = 0; r < 8; r++) acc[r] += zs[r][d] * w;
        }
        #pragma unroll
        for (int r = 0; r < 8; r++) proj[r][o] = acc[r];
    }
    __syncthreads();

    // Copy Q (scaled), K, V into global scratch
    const float scale = 0.17677669529663687f;  // 1/sqrt(32)
    for (int u = tid; u < 1024; u += 128) {
        int r = u >> 7, k = u & 127;
        int i = i0 + r; int h = k >> 5, d = k & 31;
        g_Ahat[(i * 4 + h) * 44 + d] = proj[r][k] * scale;
        g_Bhat[(i * 4 + h) * 44 + d] = proj[r][128 + k];
        g_V[i * 128 + k] = proj[r][256 + k];
    }

    // Frame transforms: one thread per (row, head)
    if (tid < 32) {
        int r = tid >> 2, h = tid & 3;
        int i = i0 + r;
        float w = log1pf(__expf(w_C[h]));
        float R[3][3], tv[3];
        #pragma unroll
        for (int x = 0; x < 3; x++) {
            #pragma unroll
            for (int y = 0; y < 3; y++) R[x][y] = T[i * 16 + x * 4 + y];
            tv[x] = T[i * 16 + x * 4 + 3];
        }
        float qq = 0.f, kk = 0.f;
        #pragma unroll
        for (int p = 0; p < 4; p++) {
            float q0 = proj[r][384 + h * 12 + p * 3 + 0];
            float q1 = proj[r][384 + h * 12 + p * 3 + 1];
            float q2 = proj[r][384 + h * 12 + p * 3 + 2];
            float k0 = proj[r][432 + h * 12 + p * 3 + 0];
            float k1 = proj[r][432 + h * 12 + p * 3 + 1];
            float k2 = proj[r][432 + h * 12 + p * 3 + 2];
            float v0 = proj[r][480 + h * 12 + p * 3 + 0];
            float v1 = proj[r][480 + h * 12 + p * 3 + 1];
            float v2 = proj[r][480 + h * 12 + p * 3 + 2];
            #pragma unroll
            for (int x = 0; x < 3; x++) {
                float gq = R[x][0] * q0 + R[x][1] * q1 + R[x][2] * q2 + tv[x];
                float gk = R[x][0] * k0 + R[x][1] * k1 + R[x][2] * k2 + tv[x];
                float gv = R[x][0] * v0 + R[x][1] * v1 + R[x][2] * v2 + tv[x];
                g_Ahat[(i * 4 + h) * 44 + 32 + p * 3 + x] = w * gq;
                g_Bhat[(i * 4 + h) * 44 + 32 + p * 3 + x] = gk;
                g_Vg[i * 48 + h * 12 + p * 3 + x] = gv;
                qq += gq * gq; kk += gk * gk;
            }
        }
        g_ci[h * 1024 + i] = -0.5f * w * qq;
        g_cj[h * 1024 + i] = -0.5f * w * kk;
    }
}

// ---------------------------------------------------------------------------
// Kernel M: per-row logits + softmax + o_pair. grid=1024 (one row), blk=256
// Pair row streamed once from DRAM; second pass expected to hit L2.
// ---------------------------------------------------------------------------
__global__ __launch_bounds__(256) void kmain(
    const float* __restrict__ pair, const float* __restrict__ Wb)
{
    __shared__ float probs[4][1024];
    __shared__ float Ahat_s[176];
    __shared__ float Wb_s[256];
    __shared__ float ci_s[4];
    __shared__ float redm[8][4];
    __shared__ float reds[8][4];
    __shared__ float partial[4][4][64];

    const int tid = threadIdx.x;
    const int i   = blockIdx.x;
    const int lane = tid & 31, wid = tid >> 5;

    if (tid < 176) Ahat_s[tid] = g_Ahat[i * 176 + tid];
    if (tid < 256) Wb_s[tid] = Wb[tid];
    if (tid < 4)   ci_s[tid] = g_ci[tid * 1024 + i];
    __syncthreads();

    const float* prow = pair + (size_t)i * 65536;

    // Pass 1: logits
    for (int jj = 0; jj < 4; jj++) {
        int j = jj * 256 + tid;
        float bh[4] = {0,0,0,0};
        const float4* p4 = (const float4*)(prow + (size_t)j * 64);
        #pragma unroll
        for (int c4 = 0; c4 < 16; c4++) {
            float4 v = p4[c4];
            const float* wb = Wb_s + c4 * 16;
            #pragma unroll
            for (int h = 0; h < 4; h++)
                bh[h] += v.x * wb[h] + v.y * wb[4 + h] + v.z * wb[8 + h] + v.w * wb[12 + h];
        }
        #pragma unroll
        for (int h = 0; h < 4; h++) {
            const float4* b4 = (const float4*)(g_Bhat + ((size_t)j * 4 + h) * 44);
            const float* A = Ahat_s + h * 44;
            float acc = 0.f;
            #pragma unroll
            for (int k4 = 0; k4 < 11; k4++) {
                float4 v = b4[k4];
                acc += v.x * A[k4 * 4] + v.y * A[k4 * 4 + 1]
                     + v.z * A[k4 * 4 + 2] + v.w * A[k4 * 4 + 3];
            }
            probs[h][j] = acc + bh[h] + ci_s[h] + g_cj[h * 1024 + j];
        }
    }
    __syncthreads();

    // Softmax: max
    #pragma unroll
    for (int h = 0; h < 4; h++) {
        float m = -1e30f;
        #pragma unroll
        for (int jj = 0; jj < 4; jj++) m = fmaxf(m, probs[h][jj * 256 + tid]);
        #pragma unroll
        for (int o = 16; o; o >>= 1) m = fmaxf(m, __shfl_xor_sync(0xffffffffu, m, o));
        if (lane == 0) redm[wid][h] = m;
    }
    __syncthreads();
    float mx[4];
    #pragma unroll
    for (int h = 0; h < 4; h++) {
        float m = redm[0][h];
        #pragma unroll
        for (int w = 1; w < 8; w++) m = fmaxf(m, redm[w][h]);
        mx[h] = m;
    }
    // exp + sum
    #pragma unroll
    for (int h = 0; h < 4; h++) {
        float s = 0.f;
        #pragma unroll
        for (int jj = 0; jj < 4; jj++) {
            int j = jj * 256 + tid;
            float e = __expf(probs[h][j] - mx[h]);
            probs[h][j] = e;
            s += e;
        }
        #pragma unroll
        for (int o = 16; o; o >>= 1) s += __shfl_xor_sync(0xffffffffu, s, o);
        if (lane == 0) reds[wid][h] = s;
    }
    __syncthreads();
    float inv[4];
    #pragma unroll
    for (int h = 0; h < 4; h++) {
        float s = 0.f;
        #pragma unroll
        for (int w = 0; w < 8; w++) s += reds[w][h];
        inv[h] = 1.0f / s;
    }
    // normalize + write attn
    #pragma unroll
    for (int jj = 0; jj < 4; jj++) {
        int j = jj * 256 + tid;
        #pragma unroll
        for (int h = 0; h < 4; h++) {
            float pv = probs[h][j] * inv[h];
            probs[h][j] = pv;
            g_attn[((size_t)h * 1024 + i) * 1024 + j] = pv;
        }
    }
    __syncthreads();

    // Pass 2: o_pair (pair row re-read, L2 hit)
    const int c = tid & 63, grp = tid >> 6;
    float acc[4] = {0,0,0,0};
    for (int j = grp; j < 1024; j += 4) {
        float p = prow[(size_t)j * 64 + c];
        #pragma unroll
        for (int h = 0; h < 4; h++) acc[h] += p * probs[h][j];
    }
    #pragma unroll
    for (int h = 0; h < 4; h++) partial[grp][h][c] = acc[h];
    __syncthreads();
    {
        int h = tid >> 6, cc = tid & 63;
        float s = partial[0][h][cc] + partial[1][h][cc]
                + partial[2][h][cc] + partial[3][h][cc];
        g_opair[i * 256 + h * 64 + cc] = s;
    }
}

// ---------------------------------------------------------------------------
// Kernel S: o_s = attn@V, o_pt_g = attn@Vg. grid = 64 i-tiles x 4 heads = 256,
// blk = 256. Tiny GEMM N=44, K=1024 per head.
// ---------------------------------------------------------------------------
__global__ __launch_bounds__(256) void kattnv()
{
    __shared__ float As[16][129];
    __shared__ float Vs[128][45];

    const int h  = blockIdx.x & 3;
    const int i0 = (blockIdx.x >> 2) * 16;
    const int tid = threadIdx.x;
    const int r  = tid & 15;
    const int nb = tid >> 4;       // 0..15
    const int n2 = nb + 32;

    float acc0 = 0.f, acc1 = 0.f, acc2 = 0.f;

    for (int j0 = 0; j0 < 1024; j0 += 128) {
        __syncthreads();
        if (tid < 128) {
            int jj = tid;
            const float4* vp = (const float4*)(g_V + (size_t)(j0 + jj) * 128 + h * 32);
            #pragma unroll
            for (int q = 0; q < 8; q++) {
                float4 v = vp[q];
                Vs[jj][q * 4 + 0] = v.x; Vs[jj][q * 4 + 1] = v.y;
                Vs[jj][q * 4 + 2] = v.z; Vs[jj][q * 4 + 3] = v.w;
            }
            const float4* gp = (const float4*)(g_Vg + (size_t)(j0 + jj) * 48 + h * 12);
            #pragma unroll
            for (int q = 0; q < 3; q++) {
                float4 v = gp[q];
                Vs[jj][32 + q * 4 + 0] = v.x; Vs[jj][32 + q * 4 + 1] = v.y;
                Vs[jj][32 + q * 4 + 2] = v.z; Vs[jj][32 + q * 4 + 3] = v.w;
            }
        } else {
            int t2 = tid - 128;
            for (int u = t2; u < 2048; u += 128) {
                int rr = u >> 7, jj = u & 127;
                As[rr][jj] = g_attn[((size_t)h * 1024 + (i0 + rr)) * 1024 + j0 + jj];
            }
        }
        __syncthreads();
        #pragma unroll 8
        for (int jj = 0; jj < 128; jj++) {
            float a = As[r][jj];
            acc0 += a * Vs[jj][nb];
            acc1 += a * Vs[jj][nb + 16];
            acc2 += a * Vs[jj][n2];   // garbage for n2>=44, never stored
        }
    }
    int i = i0 + r;
    g_os[i * 128 + h * 32 + nb]      = acc0;
    g_os[i * 128 + h * 32 + nb + 16] = acc1;
    if (n2 < 44) g_optg[i * 48 + h * 12 + (n2 - 32)] = acc2;
}

// ---------------------------------------------------------------------------
// Kernel F: o_pt rotation+norm, concat, out = single + f@Wout + b_out.
// grid=128 (8 rows/block), blk=128.
// ---------------------------------------------------------------------------
__global__ __launch_bounds__(128) void kfinal(
    const float* __restrict__ single, const float* __restrict__ T,
    const float* __restrict__ Wout,   const float* __restrict__ b_out,
    float* __restrict__ out)
{
    __shared__ float fs[8][448];
    const int tid = threadIdx.x;
    const int i0  = blockIdx.x * 8;

    for (int u = tid; u < 1024; u += 128) {
        int r = u >> 7, k = u & 127;
        fs[r][k] = g_os[(i0 + r) * 128 + k];
    }
    for (int u = tid; u < 2048; u += 128) {
        int r = u >> 8, k = u & 255;
        fs[r][128 + k] = g_opair[(i0 + r) * 256 + k];
    }
    {
        int r = tid >> 4, hp = tid & 15, h = hp >> 2, p = hp & 3;
        int i = i0 + r;
        float Rm[3][3], tv[3];
        #pragma unroll
        for (int y = 0; y < 3; y++) {
            #pragma unroll
            for (int x = 0; x < 3; x++) Rm[y][x] = T[i * 16 + y * 4 + x];
            tv[y] = T[i * 16 + y * 4 + 3];
        }
        float g0 = g_optg[i * 48 + h * 12 + p * 3 + 0] - tv[0];
        float g1 = g_optg[i * 48 + h * 12 + p * 3 + 1] - tv[1];
        float g2 = g_optg[i * 48 + h * 12 + p * 3 + 2] - tv[2];
        float nrm = 0.f;
        #pragma unroll
        for (int x = 0; x < 3; x++) {
            float v = Rm[0][x] * g0 + Rm[1][x] * g1 + Rm[2][x] * g2;
            fs[r][384 + h * 12 + p * 3 + x] = v;
            nrm += v * v;
        }
        fs[r][432 + h * 4 + p] = sqrtf(nrm);
    }
    __syncthreads();

    float acc[8] = {0,0,0,0,0,0,0,0};
    for (int k = 0; k < 448; k++) {
        float w = Wout[k * 128 + tid];
        #pragma unroll
        for (int r = 0; r < 8; r++) acc[r] += fs[r][k] * w;
    }
    float bo = b_out[tid];
    #pragma unroll
    for (int r = 0; r < 8; r++)
        out[(i0 + r) * 128 + tid] = single[(i0 + r) * 128 + tid] + acc[r] + bo;
}

// ---------------------------------------------------------------------------
extern "C" void kernel_launch(void* const* d_in, const int* in_sizes, int n_in,
                              void* d_out, int out_size)
{
    const float* single = (const float*)d_in[0];
    const float* pair   = (const float*)d_in[1];
    const float* T      = (const float*)d_in[2];
    const float* w_C    = (const float*)d_in[3];
    const float* ln_g   = (const float*)d_in[4];
    const float* ln_b   = (const float*)d_in[5];
    const float* Wq     = (const float*)d_in[6];
    const float* Wk     = (const float*)d_in[7];
    const float* Wv     = (const float*)d_in[8];
    const float* Wqpt   = (const float*)d_in[9];
    const float* Wkpt   = (const float*)d_in[10];
    const float* Wvpt   = (const float*)d_in[11];
    const float* Wb     = (const float*)d_in[12];
    const float* Wout   = (const float*)d_in[13];
    const float* b_out  = (const float*)d_in[14];
    float* out = (float*)d_out;

    kprep<<<128, 128>>>(single, T, w_C, ln_g, ln_b, Wq, Wk, Wv, Wqpt, Wkpt, Wvpt);
    kmain<<<1024, 256>>>(pair, Wb);
    kattnv<<<256, 256>>>();
    kfinal<<<128, 128>>>(single, T, Wout, b_out, out);
}

// round 3
// speedup vs baseline: 1.4209x; 1.4209x over previous
#include <cuda_runtime.h>
#include <math.h>

// Scratch (static device globals; allocation-free)
__device__ float g_Ahat[1024 * 176];        // [i][h*44+k]  = [Q*scale | w*Qg]
__device__ float g_BhatT[44 * 1024 * 4];    // [k4][j][4]   = [K | Kg] transposed
__device__ float g_cih[1024 * 4];           // [i][h] -0.5*w*|Qg|^2
__device__ float g_cjh[1024 * 4];           // [j][h] -0.5*w*|Kg|^2
__device__ float g_Vcat[1024 * 176];        // [j][ V(128) | Vg(48) ]
__device__ float g_bat[(size_t)1024 * 1024 * 4]; // [i][j][h] pair@Wb, 16MB
__device__ float g_os[1024 * 128];
__device__ float g_optg[1024 * 48];
__device__ float g_opair[1024 * 256];

// ---------------------------------------------------------------------------
// kprep: layernorm + projections + frame transforms. grid=256 (4 rows), blk=128
// ---------------------------------------------------------------------------
__global__ __launch_bounds__(128) void kprep(
    const float* __restrict__ single, const float* __restrict__ T,
    const float* __restrict__ w_C,    const float* __restrict__ ln_g,
    const float* __restrict__ ln_b,
    const float* __restrict__ Wq, const float* __restrict__ Wk,
    const float* __restrict__ Wv, const float* __restrict__ Wqpt,
    const float* __restrict__ Wkpt, const float* __restrict__ Wvpt)
{
    __shared__ float zs[128 * 4];    // [d][r]
    __shared__ float proj[4][528];
    __shared__ float red[2][4];

    const int tid = threadIdx.x;
    const int i0  = blockIdx.x * 4;
    const int lane = tid & 31, wid = tid >> 5;

    for (int r = 0; r < 4; r++) {
        float x = single[(i0 + r) * 128 + tid];
        float s = x, s2 = x * x;
        #pragma unroll
        for (int o = 16; o; o >>= 1) {
            s  += __shfl_xor_sync(0xffffffffu, s,  o);
            s2 += __shfl_xor_sync(0xffffffffu, s2, o);
        }
        if (lane == 0) { red[0][wid] = s; red[1][wid] = s2; }
        __syncthreads();
        float sum  = red[0][0] + red[0][1] + red[0][2] + red[0][3];
        float sum2 = red[1][0] + red[1][1] + red[1][2] + red[1][3];
        float mu  = sum * (1.f / 128.f);
        float var = sum2 * (1.f / 128.f) - mu * mu;
        float inv = rsqrtf(var + 1e-5f);
        zs[tid * 4 + r] = (x - mu) * inv * ln_g[tid] + ln_b[tid];
        __syncthreads();
    }

    // Projections: 528 outputs/row
    for (int o = tid; o < 528; o += 128) {
        const float* W; int col, ow;
        if      (o < 128) { W = Wq;   col = o;       ow = 128; }
        else if (o < 256) { W = Wk;   col = o - 128; ow = 128; }
        else if (o < 384) { W = Wv;   col = o - 256; ow = 128; }
        else if (o < 432) { W = Wqpt; col = o - 384; ow = 48;  }
        else if (o < 480) { W = Wkpt; col = o - 432; ow = 48;  }
        else              { W = Wvpt; col = o - 480; ow = 48;  }
        float a0 = 0.f, a1 = 0.f, a2 = 0.f, a3 = 0.f;
        #pragma unroll 4
        for (int d = 0; d < 128; d++) {
            float w = W[d * ow + col];
            float4 z = *(const float4*)&zs[d * 4];
            a0 += z.x * w; a1 += z.y * w; a2 += z.z * w; a3 += z.w * w;
        }
        proj[0][o] = a0; proj[1][o] = a1; proj[2][o] = a2; proj[3][o] = a3;
    }
    __syncthreads();

    const float scale = 0.17677669529663687f;   // 1/sqrt(32)
    for (int u = tid; u < 512; u += 128) {
        int r = u >> 7, k = u & 127;
        int i = i0 + r, h = k >> 5, d = k & 31;
        int kk = h * 44 + d;
        g_Ahat[i * 176 + kk] = proj[r][k] * scale;
        g_BhatT[(kk >> 2) * 4096 + i * 4 + (kk & 3)] = proj[r][128 + k];
        g_Vcat[i * 176 + k] = proj[r][256 + k];
    }

    if (tid < 16) {
        int r = tid >> 2, h = tid & 3;
        int i = i0 + r;
        float w = log1pf(__expf(w_C[h]));
        float R[3][3], tv[3];
        #pragma unroll
        for (int x = 0; x < 3; x++) {
            #pragma unroll
            for (int y = 0; y < 3; y++) R[x][y] = T[i * 16 + x * 4 + y];
            tv[x] = T[i * 16 + x * 4 + 3];
        }
        float qq = 0.f, kk2 = 0.f;
        #pragma unroll
        for (int p = 0; p < 4; p++) {
            float q0 = proj[r][384 + h * 12 + p * 3 + 0];
            float q1 = proj[r][384 + h * 12 + p * 3 + 1];
            float q2 = proj[r][384 + h * 12 + p * 3 + 2];
            float k0 = proj[r][432 + h * 12 + p * 3 + 0];
            float k1 = proj[r][432 + h * 12 + p * 3 + 1];
            float k2 = proj[r][432 + h * 12 + p * 3 + 2];
            float v0 = proj[r][480 + h * 12 + p * 3 + 0];
            float v1 = proj[r][480 + h * 12 + p * 3 + 1];
            float v2 = proj[r][480 + h * 12 + p * 3 + 2];
            #pragma unroll
            for (int x = 0; x < 3; x++) {
                float gq = R[x][0] * q0 + R[x][1] * q1 + R[x][2] * q2 + tv[x];
                float gk = R[x][0] * k0 + R[x][1] * k1 + R[x][2] * k2 + tv[x];
                float gv = R[x][0] * v0 + R[x][1] * v1 + R[x][2] * v2 + tv[x];
                int kki = h * 44 + 32 + p * 3 + x;
                g_Ahat[i * 176 + kki] = w * gq;
                g_BhatT[(kki >> 2) * 4096 + i * 4 + (kki & 3)] = gk;
                g_Vcat[i * 176 + 128 + h * 12 + p * 3 + x] = gv;
                qq += gq * gq; kk2 += gk * gk;
            }
        }
        g_cih[i * 4 + h] = -0.5f * w * qq;
        g_cjh[i * 4 + h] = -0.5f * w * kk2;
    }
}

// ---------------------------------------------------------------------------
// kbias: b = pair @ Wb, coalesced streaming GEMM. grid=8192, blk=128
// ---------------------------------------------------------------------------
__global__ __launch_bounds__(128) void kbias(
    const float* __restrict__ pair, const float* __restrict__ Wb)
{
    __shared__ float ps[128 * 68];   // 128 flat rows x 64 c, padded
    __shared__ float wbs[256];

    const int tid = threadIdx.x;
    const size_t base = (size_t)blockIdx.x * 128;

    for (int u = tid; u < 256; u += 128) wbs[u] = Wb[u];

    const float4* src = (const float4*)(pair + base * 64);
    #pragma unroll 4
    for (int u = tid; u < 2048; u += 128) {
        float4 v = src[u];
        int row = u >> 4, c4 = u & 15;
        *(float4*)&ps[row * 68 + c4 * 4] = v;
    }
    __syncthreads();

    float b0 = 0.f, b1 = 0.f, b2 = 0.f, b3 = 0.f;
    #pragma unroll
    for (int k = 0; k < 16; k++) {
        float4 q = *(const float4*)&ps[tid * 68 + k * 4];
        const float* w = wbs + k * 16;
        b0 += q.x * w[0] + q.y * w[4] + q.z * w[8]  + q.w * w[12];
        b1 += q.x * w[1] + q.y * w[5] + q.z * w[9]  + q.w * w[13];
        b2 += q.x * w[2] + q.y * w[6] + q.z * w[10] + q.w * w[14];
        b3 += q.x * w[3] + q.y * w[7] + q.z * w[11] + q.w * w[15];
    }
    ((float4*)g_bat)[base + tid] = make_float4(b0, b1, b2, b3);
}

// ---------------------------------------------------------------------------
// kmain: logits + softmax + o_pair + o_s + o_pt_g.
// grid=256 (4 rows/block), blk=256, dynamic smem (~69.5KB)
// ---------------------------------------------------------------------------
__global__ __launch_bounds__(256) void kmain(const float* __restrict__ pair)
{
    extern __shared__ float smem[];
    float* probs = smem;                 // 16384  [r][h][1024] (exp, unnormalized)
    float* Ahat  = smem + 16384;         // 704    [r][176]
    float* cis   = Ahat + 704;           // 16     [r*4+h]
    float* redm  = cis + 16;             // 128    [wid][16]
    float* reds  = redm + 128;           // 128    [wid][16]
    float* partial = probs;              // reuse after probs is dead

    const int t = threadIdx.x;
    const int i0 = blockIdx.x * 4;
    const int lane = t & 31, wid = t >> 5;

    for (int u = t; u < 704; u += 256) Ahat[u] = g_Ahat[i0 * 176 + u];
    if (t < 16) cis[t] = g_cih[i0 * 4 + t];
    __syncthreads();

    const float4* bhat4 = (const float4*)g_BhatT;
    const float4* bat4  = (const float4*)g_bat;
    const float4* cjh4  = (const float4*)g_cjh;

    // ---- pass 1: logits ----
    for (int jj = 0; jj < 4; jj++) {
        int j = jj * 256 + t;
        float acc[4][4];
        #pragma unroll
        for (int r = 0; r < 4; r++)
            #pragma unroll
            for (int h = 0; h < 4; h++) acc[r][h] = 0.f;

        #pragma unroll
        for (int k4 = 0; k4 < 44; k4++) {
            const int h = k4 / 11;
            float4 bv = bhat4[k4 * 1024 + j];
            #pragma unroll
            for (int r = 0; r < 4; r++) {
                float4 av = *(const float4*)&Ahat[r * 176 + k4 * 4];
                acc[r][h] += av.x * bv.x + av.y * bv.y + av.z * bv.z + av.w * bv.w;
            }
        }
        float4 cj = cjh4[j];
        #pragma unroll
        for (int r = 0; r < 4; r++) {
            float4 bb = bat4[(size_t)(i0 + r) * 1024 + j];
            probs[(r * 4 + 0) * 1024 + j] = acc[r][0] + bb.x + cis[r * 4 + 0] + cj.x;
            probs[(r * 4 + 1) * 1024 + j] = acc[r][1] + bb.y + cis[r * 4 + 1] + cj.y;
            probs[(r * 4 + 2) * 1024 + j] = acc[r][2] + bb.z + cis[r * 4 + 2] + cj.z;
            probs[(r * 4 + 3) * 1024 + j] = acc[r][3] + bb.w + cis[r * 4 + 3] + cj.w;
        }
    }
    __syncthreads();

    // ---- softmax (leave exp unnormalized; fold 1/Z into epilogues) ----
    float mx[16];
    #pragma unroll
    for (int rh = 0; rh < 16; rh++) {
        float m = -1e30f;
        #pragma unroll
        for (int jj = 0; jj < 4; jj++) m = fmaxf(m, probs[rh * 1024 + jj * 256 + t]);
        #pragma unroll
        for (int o = 16; o; o >>= 1) m = fmaxf(m, __shfl_xor_sync(0xffffffffu, m, o));
        if (lane == 0) redm[wid * 16 + rh] = m;
    }
    __syncthreads();
    #pragma unroll
    for (int rh = 0; rh < 16; rh++) {
        float m = redm[rh];
        #pragma unroll
        for (int w = 1; w < 8; w++) m = fmaxf(m, redm[w * 16 + rh]);
        mx[rh] = m;
    }
    #pragma unroll
    for (int rh = 0; rh < 16; rh++) {
        float s = 0.f;
        #pragma unroll
        for (int jj = 0; jj < 4; jj++) {
            int j = jj * 256 + t;
            float e = __expf(probs[rh * 1024 + j] - mx[rh]);
            probs[rh * 1024 + j] = e;
            s += e;
        }
        #pragma unroll
        for (int o = 16; o; o >>= 1) s += __shfl_xor_sync(0xffffffffu, s, o);
        if (lane == 0) reds[wid * 16 + rh] = s;
    }
    __syncthreads();

    // ---- epilogue B accumulate: o_pair (second pair stream, coalesced) ----
    const int c = t & 63, g = t >> 6;
    float accB[4][4];
    #pragma unroll
    for (int r = 0; r < 4; r++)
        #pragma unroll
        for (int h = 0; h < 4; h++) accB[r][h] = 0.f;

    #pragma unroll
    for (int r = 0; r < 4; r++) {
        const float* prow = pair + (size_t)(i0 + r) * 65536 + c;
        for (int j = g; j < 1024; j += 16) {
            float p0 = prow[(j + 0) * 64];
            float p1 = prow[(j + 4) * 64];
            float p2 = prow[(j + 8) * 64];
            float p3 = prow[(j + 12) * 64];
            #pragma unroll
            for (int h = 0; h < 4; h++) {
                accB[r][h] += probs[(r * 4 + h) * 1024 + j] * p0
                            + probs[(r * 4 + h) * 1024 + j + 4] * p1
                            + probs[(r * 4 + h) * 1024 + j + 8] * p2
                            + probs[(r * 4 + h) * 1024 + j + 12] * p3;
            }
        }
    }

    // ---- epilogue A: o_s and o_pt_g (Vcat coalesced from L2) ----
    if (t < 176) {
        const int h = (t < 128) ? (t >> 5) : ((t - 128) / 12);
        float acc[4] = {0.f, 0.f, 0.f, 0.f};
        for (int j = 0; j < 1024; j += 4) {
            float v0 = g_Vcat[(j + 0) * 176 + t];
            float v1 = g_Vcat[(j + 1) * 176 + t];
            float v2 = g_Vcat[(j + 2) * 176 + t];
            float v3 = g_Vcat[(j + 3) * 176 + t];
            #pragma unroll
            for (int r = 0; r < 4; r++) {
                const float* pr = probs + (r * 4 + h) * 1024 + j;
                acc[r] += pr[0] * v0 + pr[1] * v1 + pr[2] * v2 + pr[3] * v3;
            }
        }
        #pragma unroll
        for (int r = 0; r < 4; r++) {
            float s = 0.f;
            #pragma unroll
            for (int w = 0; w < 8; w++) s += reds[w * 16 + r * 4 + h];
            float val = acc[r] / s;
            int i = i0 + r;
            if (t < 128) g_os[i * 128 + t] = val;
            else         g_optg[i * 48 + (t - 128)] = val;
        }
    }
    __syncthreads();   // all probs reads done

    // ---- o_pair cross-group reduce (reuses probs region) ----
    #pragma unroll
    for (int r = 0; r < 4; r++)
        #pragma unroll
        for (int h = 0; h < 4; h++)
            partial[((g * 4 + r) * 4 + h) * 64 + c] = accB[r][h];
    __syncthreads();
    {
        const int c2 = t & 63, h2 = t >> 6;
        #pragma unroll
        for (int r = 0; r < 4; r++) {
            float s = partial[((0 * 4 + r) * 4 + h2) * 64 + c2]
                    + partial[((1 * 4 + r) * 4 + h2) * 64 + c2]
                    + partial[((2 * 4 + r) * 4 + h2) * 64 + c2]
                    + partial[((3 * 4 + r) * 4 + h2) * 64 + c2];
            float z = 0.f;
            #pragma unroll
            for (int w = 0; w < 8; w++) z += reds[w * 16 + r * 4 + h2];
            g_opair[(i0 + r) * 256 + h2 * 64 + c2] = s / z;
        }
    }
}

// ---------------------------------------------------------------------------
// kfinal: rotation+norm, concat, out = single + f@Wout + b_out.
// grid=256 (4 rows/block), blk=256
// ---------------------------------------------------------------------------
__global__ __launch_bounds__(256) void kfinal(
    const float* __restrict__ single, const float* __restrict__ T,
    const float* __restrict__ Wout,   const float* __restrict__ b_out,
    float* __restrict__ out)
{
    __shared__ float fs[448 * 4];      // [k][r]
    __shared__ float part[2 * 4 * 128];

    const int tid = threadIdx.x;
    const int i0  = blockIdx.x * 4;

    for (int u = tid; u < 512; u += 256) {
        int r = u & 3, k = u >> 2;
        fs[k * 4 + r] = g_os[(i0 + r) * 128 + k];
    }
    for (int u = tid; u < 1024; u += 256) {
        int r = u & 3, k2 = u >> 2;
        fs[(128 + k2) * 4 + r] = g_opair[(i0 + r) * 256 + k2];
    }
    if (tid < 64) {
        int r = tid >> 4, hp = tid & 15, h = hp >> 2, p = hp & 3;
        int i = i0 + r;
        float Rm[3][3], tv[3];
        #pragma unroll
        for (int y = 0; y < 3; y++) {
            #pragma unroll
            for (int x = 0; x < 3; x++) Rm[y][x] = T[i * 16 + y * 4 + x];
            tv[y] = T[i * 16 + y * 4 + 3];
        }
        float g0 = g_optg[i * 48 + h * 12 + p * 3 + 0] - tv[0];
        float g1 = g_optg[i * 48 + h * 12 + p * 3 + 1] - tv[1];
        float g2 = g_optg[i * 48 + h * 12 + p * 3 + 2] - tv[2];
        float nrm = 0.f;
        #pragma unroll
        for (int x = 0; x < 3; x++) {
            float v = Rm[0][x] * g0 + Rm[1][x] * g1 + Rm[2][x] * g2;
            fs[(384 + h * 12 + p * 3 + x) * 4 + r] = v;
            nrm += v * v;
        }
        fs[(432 + h * 4 + p) * 4 + r] = sqrtf(nrm);
    }
    __syncthreads();

    const int d = tid & 127, half = tid >> 7;
    float a0 = 0.f, a1 = 0.f, a2 = 0.f, a3 = 0.f;
    const int k0 = half * 224;
    #pragma unroll 4
    for (int k = k0; k < k0 + 224; k++) {
        float w = Wout[k * 128 + d];
        float4 f = *(const float4*)&fs[k * 4];
        a0 += f.x * w; a1 += f.y * w; a2 += f.z * w; a3 += f.w * w;
    }
    part[(half * 4 + 0) * 128 + d] = a0;
    part[(half * 4 + 1) * 128 + d] = a1;
    part[(half * 4 + 2) * 128 + d] = a2;
    part[(half * 4 + 3) * 128 + d] = a3;
    __syncthreads();

    if (tid < 128) {
        float bo = b_out[tid];
        #pragma unroll
        for (int r = 0; r < 4; r++) {
            float s = part[r * 128 + tid] + part[(4 + r) * 128 + tid];
            out[(i0 + r) * 128 + tid] = single[(i0 + r) * 128 + tid] + s + bo;
        }
    }
}

// ---------------------------------------------------------------------------
extern "C" void kernel_launch(void* const* d_in, const int* in_sizes, int n_in,
                              void* d_out, int out_size)
{
    const float* single = (const float*)d_in[0];
    const float* pair   = (const float*)d_in[1];
    const float* T      = (const float*)d_in[2];
    const float* w_C    = (const float*)d_in[3];
    const float* ln_g   = (const float*)d_in[4];
    const float* ln_b   = (const float*)d_in[5];
    const float* Wq     = (const float*)d_in[6];
    const float* Wk     = (const float*)d_in[7];
    const float* Wv     = (const float*)d_in[8];
    const float* Wqpt   = (const float*)d_in[9];
    const float* Wkpt   = (const float*)d_in[10];
    const float* Wvpt   = (const float*)d_in[11];
    const float* Wb     = (const float*)d_in[12];
    const float* Wout   = (const float*)d_in[13];
    const float* b_out  = (const float*)d_in[14];
    float* out = (float*)d_out;

    static int smem_set = 0;
    const int kmain_smem = (16384 + 704 + 16 + 128 + 128) * 4;  // 69440 B
    if (!smem_set) {
        cudaFuncSetAttribute(kmain, cudaFuncAttributeMaxDynamicSharedMemorySize,
                             kmain_smem);
        smem_set = 1;
    }

    kprep<<<256, 128>>>(single, T, w_C, ln_g, ln_b, Wq, Wk, Wv, Wqpt, Wkpt, Wvpt);
    kbias<<<8192, 128>>>(pair, Wb);
    kmain<<<256, 256, kmain_smem>>>(pair);
    kfinal<<<256, 256>>>(single, T, Wout, b_out, out);
}

// round 4
// speedup vs baseline: 2.3920x; 1.6834x over previous
#include <cuda_runtime.h>
#include <math.h>

// Scratch (static device globals; allocation-free)
__device__ float g_Ahat[1024 * 176];          // [i][h*44+k] = [Q*scale | w*Qg]
__device__ float g_BhatT[44 * 1024 * 4];      // [k4][j][4]  = [K | Kg] transposed
__device__ float g_cjh[1024 * 4];             // [j][h] -0.5*w*|Kg|^2
__device__ float g_Vcat[1024 * 176];          // [j][ V(128) | Vg(48) ]
__device__ float g_bat[(size_t)1024 * 1024 * 4];  // [i][j][h] pair@Wb (16MB)
__device__ float g_attn[(size_t)4 * 1024 * 1024]; // [h][i][j] normalized (16MB)
__device__ float g_os[1024 * 128];
__device__ float g_optg[1024 * 48];
__device__ float g_opair[1024 * 256];

// ---------------------------------------------------------------------------
// kprep: layernorm + projections + frame transforms. grid=256 (4 rows), blk=256
// ---------------------------------------------------------------------------
__global__ __launch_bounds__(256) void kprep(
    const float* __restrict__ single, const float* __restrict__ T,
    const float* __restrict__ w_C,    const float* __restrict__ ln_g,
    const float* __restrict__ ln_b,
    const float* __restrict__ Wq, const float* __restrict__ Wk,
    const float* __restrict__ Wv, const float* __restrict__ Wqpt,
    const float* __restrict__ Wkpt, const float* __restrict__ Wvpt)
{
    __shared__ float zs[128 * 4];    // [d][r]
    __shared__ float proj[4][528];
    __shared__ float red[2][8];

    const int t  = threadIdx.x;
    const int i0 = blockIdx.x * 4;
    const int lane = t & 31, wid = t >> 5;

    // Layernorm: two rows per pass (256 threads = 2 rows x 128 dims)
    for (int pass = 0; pass < 2; pass++) {
        const int r = pass * 2 + (t >> 7);
        const int d = t & 127;
        float x = single[(i0 + r) * 128 + d];
        float s = x, s2 = x * x;
        #pragma unroll
        for (int o = 16; o; o >>= 1) {
            s  += __shfl_xor_sync(0xffffffffu, s,  o);
            s2 += __shfl_xor_sync(0xffffffffu, s2, o);
        }
        if (lane == 0) { red[0][wid] = s; red[1][wid] = s2; }
        __syncthreads();
        const int base = (t >> 7) * 4;
        float sum  = red[0][base] + red[0][base+1] + red[0][base+2] + red[0][base+3];
        float sum2 = red[1][base] + red[1][base+1] + red[1][base+2] + red[1][base+3];
        float mu  = sum * (1.f / 128.f);
        float var = sum2 * (1.f / 128.f) - mu * mu;
        float inv = rsqrtf(var + 1e-5f);
        zs[d * 4 + r] = (x - mu) * inv * ln_g[d] + ln_b[d];
        __syncthreads();
    }

    // Projections: 528 outputs/row, 256 threads
    for (int o = t; o < 528; o += 256) {
        const float* W; int col, ow;
        if      (o < 128) { W = Wq;   col = o;       ow = 128; }
        else if (o < 256) { W = Wk;   col = o - 128; ow = 128; }
        else if (o < 384) { W = Wv;   col = o - 256; ow = 128; }
        else if (o < 432) { W = Wqpt; col = o - 384; ow = 48;  }
        else if (o < 480) { W = Wkpt; col = o - 432; ow = 48;  }
        else              { W = Wvpt; col = o - 480; ow = 48;  }
        float a0 = 0.f, a1 = 0.f, a2 = 0.f, a3 = 0.f;
        #pragma unroll 8
        for (int d = 0; d < 128; d++) {
            float w = W[d * ow + col];
            float4 z = *(const float4*)&zs[d * 4];
            a0 += z.x * w; a1 += z.y * w; a2 += z.z * w; a3 += z.w * w;
        }
        proj[0][o] = a0; proj[1][o] = a1; proj[2][o] = a2; proj[3][o] = a3;
    }
    __syncthreads();

    const float scale = 0.17677669529663687f;   // 1/sqrt(32)
    for (int u = t; u < 512; u += 256) {
        int r = u >> 7, k = u & 127;
        int i = i0 + r, h = k >> 5, d = k & 31;
        int kk = h * 44 + d;
        g_Ahat[i * 176 + kk] = proj[r][k] * scale;
        g_BhatT[(kk >> 2) * 4096 + i * 4 + (kk & 3)] = proj[r][128 + k];
        g_Vcat[i * 176 + k] = proj[r][256 + k];
    }

    if (t < 16) {
        int r = t >> 2, h = t & 3;
        int i = i0 + r;
        float w = log1pf(__expf(w_C[h]));
        float R[3][3], tv[3];
        #pragma unroll
        for (int x = 0; x < 3; x++) {
            #pragma unroll
            for (int y = 0; y < 3; y++) R[x][y] = T[i * 16 + x * 4 + y];
            tv[x] = T[i * 16 + x * 4 + 3];
        }
        float kk2 = 0.f;
        #pragma unroll
        for (int p = 0; p < 4; p++) {
            float q0 = proj[r][384 + h * 12 + p * 3 + 0];
            float q1 = proj[r][384 + h * 12 + p * 3 + 1];
            float q2 = proj[r][384 + h * 12 + p * 3 + 2];
            float k0 = proj[r][432 + h * 12 + p * 3 + 0];
            float k1 = proj[r][432 + h * 12 + p * 3 + 1];
            float k2 = proj[r][432 + h * 12 + p * 3 + 2];
            float v0 = proj[r][480 + h * 12 + p * 3 + 0];
            float v1 = proj[r][480 + h * 12 + p * 3 + 1];
            float v2 = proj[r][480 + h * 12 + p * 3 + 2];
            #pragma unroll
            for (int x = 0; x < 3; x++) {
                float gq = R[x][0] * q0 + R[x][1] * q1 + R[x][2] * q2 + tv[x];
                float gk = R[x][0] * k0 + R[x][1] * k1 + R[x][2] * k2 + tv[x];
                float gv = R[x][0] * v0 + R[x][1] * v1 + R[x][2] * v2 + tv[x];
                int kki = h * 44 + 32 + p * 3 + x;
                g_Ahat[i * 176 + kki] = w * gq;
                g_BhatT[(kki >> 2) * 4096 + i * 4 + (kki & 3)] = gk;
                g_Vcat[i * 176 + 128 + h * 12 + p * 3 + x] = gv;
                kk2 += gk * gk;
            }
        }
        g_cjh[i * 4 + h] = -0.5f * w * kk2;
    }
}

// ---------------------------------------------------------------------------
// kbias: b = pair @ Wb, coalesced streaming GEMM. grid=8192, blk=128
// ---------------------------------------------------------------------------
__global__ __launch_bounds__(128) void kbias(
    const float* __restrict__ pair, const float* __restrict__ Wb)
{
    __shared__ float ps[128 * 68];
    __shared__ float wbs[256];

    const int tid = threadIdx.x;
    const size_t base = (size_t)blockIdx.x * 128;

    for (int u = tid; u < 256; u += 128) wbs[u] = Wb[u];

    const float4* src = (const float4*)(pair + base * 64);
    #pragma unroll
    for (int q = 0; q < 16; q++) {
        int u = q * 128 + tid;
        float4 v = src[u];
        int row = u >> 4, c4 = u & 15;
        *(float4*)&ps[row * 68 + c4 * 4] = v;
    }
    __syncthreads();

    float b0 = 0.f, b1 = 0.f, b2 = 0.f, b3 = 0.f;
    #pragma unroll
    for (int k = 0; k < 16; k++) {
        float4 q = *(const float4*)&ps[tid * 68 + k * 4];
        const float* w = wbs + k * 16;
        b0 += q.x * w[0] + q.y * w[4] + q.z * w[8]  + q.w * w[12];
        b1 += q.x * w[1] + q.y * w[5] + q.z * w[9]  + q.w * w[13];
        b2 += q.x * w[2] + q.y * w[6] + q.z * w[10] + q.w * w[14];
        b3 += q.x * w[3] + q.y * w[7] + q.z * w[11] + q.w * w[15];
    }
    ((float4*)g_bat)[base + tid] = make_float4(b0, b1, b2, b3);
}

// ---------------------------------------------------------------------------
// klogits: logits + softmax -> normalized probs to g_attn[h][i][j].
// grid=256 (4 rows/block), blk=256, dyn smem ~68KB
// ---------------------------------------------------------------------------
__global__ __launch_bounds__(256) void klogits()
{
    extern __shared__ float smem[];
    float* probs = smem;               // 16384  [r*4+h][1024]
    float* Ahat  = smem + 16384;       // 704
    float* redm  = Ahat + 704;         // 128 [wid][16]
    float* reds  = redm + 128;         // 128

    const int t = threadIdx.x;
    const int i0 = blockIdx.x * 4;
    const int lane = t & 31, wid = t >> 5;

    for (int u = t; u < 704; u += 256) Ahat[u] = g_Ahat[i0 * 176 + u];
    __syncthreads();

    const float4* bhat4 = (const float4*)g_BhatT;
    const float4* bat4  = (const float4*)g_bat;
    const float4* cjh4  = (const float4*)g_cjh;

    // logits
    for (int jj = 0; jj < 4; jj++) {
        int j = jj * 256 + t;
        float acc[4][4];
        #pragma unroll
        for (int r = 0; r < 4; r++)
            #pragma unroll
            for (int h = 0; h < 4; h++) acc[r][h] = 0.f;

        #pragma unroll
        for (int k4 = 0; k4 < 44; k4++) {
            const int h = k4 / 11;
            float4 bv = bhat4[k4 * 1024 + j];
            #pragma unroll
            for (int r = 0; r < 4; r++) {
                float4 av = *(const float4*)&Ahat[r * 176 + k4 * 4];
                acc[r][h] += av.x * bv.x + av.y * bv.y + av.z * bv.z + av.w * bv.w;
            }
        }
        float4 cj = cjh4[j];
        #pragma unroll
        for (int r = 0; r < 4; r++) {
            float4 bb = bat4[(size_t)(i0 + r) * 1024 + j];
            probs[(r * 4 + 0) * 1024 + j] = acc[r][0] + bb.x + cj.x;
            probs[(r * 4 + 1) * 1024 + j] = acc[r][1] + bb.y + cj.y;
            probs[(r * 4 + 2) * 1024 + j] = acc[r][2] + bb.z + cj.z;
            probs[(r * 4 + 3) * 1024 + j] = acc[r][3] + bb.w + cj.w;
        }
    }
    __syncthreads();

    // softmax
    float mx[16];
    #pragma unroll
    for (int rh = 0; rh < 16; rh++) {
        float m = -1e30f;
        #pragma unroll
        for (int jj = 0; jj < 4; jj++) m = fmaxf(m, probs[rh * 1024 + jj * 256 + t]);
        #pragma unroll
        for (int o = 16; o; o >>= 1) m = fmaxf(m, __shfl_xor_sync(0xffffffffu, m, o));
        if (lane == 0) redm[wid * 16 + rh] = m;
    }
    __syncthreads();
    #pragma unroll
    for (int rh = 0; rh < 16; rh++) {
        float m = redm[rh];
        #pragma unroll
        for (int w = 1; w < 8; w++) m = fmaxf(m, redm[w * 16 + rh]);
        mx[rh] = m;
    }
    #pragma unroll
    for (int rh = 0; rh < 16; rh++) {
        float s = 0.f;
        #pragma unroll
        for (int jj = 0; jj < 4; jj++) {
            int j = jj * 256 + t;
            float e = __expf(probs[rh * 1024 + j] - mx[rh]);
            probs[rh * 1024 + j] = e;
            s += e;
        }
        #pragma unroll
        for (int o = 16; o; o >>= 1) s += __shfl_xor_sync(0xffffffffu, s, o);
        if (lane == 0) reds[wid * 16 + rh] = s;
    }
    __syncthreads();
    float invZ[16];
    #pragma unroll
    for (int rh = 0; rh < 16; rh++) {
        float s = 0.f;
        #pragma unroll
        for (int w = 0; w < 8; w++) s += reds[w * 16 + rh];
        invZ[rh] = 1.0f / s;
    }

    // normalized write to g_attn[h][i][j]
    #pragma unroll
    for (int jj = 0; jj < 4; jj++) {
        int j = jj * 256 + t;
        #pragma unroll
        for (int r = 0; r < 4; r++)
            #pragma unroll
            for (int h = 0; h < 4; h++)
                g_attn[((size_t)h * 1024 + (i0 + r)) * 1024 + j] =
                    probs[(r * 4 + h) * 1024 + j] * invZ[r * 4 + h];
    }
}

// ---------------------------------------------------------------------------
// kopair: o_pair = attn @ pair. grid=1024 (one row i), blk=256
// ---------------------------------------------------------------------------
__global__ __launch_bounds__(256) void kopair(const float* __restrict__ pair)
{
    __shared__ float ps[4 * 1024];     // [h][j]
    __shared__ float red[4 * 4 * 64];  // [g][h][c]

    const int t = threadIdx.x;
    const int i = blockIdx.x;

    #pragma unroll
    for (int q = 0; q < 16; q++) {
        int u = q * 256 + t;
        ps[u] = g_attn[((size_t)(u >> 10) * 1024 + i) * 1024 + (u & 1023)];
    }
    __syncthreads();

    const int c = t & 63, g = t >> 6;
    const float* prow = pair + (size_t)i * 65536 + c;
    float acc[4] = {0.f, 0.f, 0.f, 0.f};

    for (int j = g; j < 1024; j += 16) {
        float p0 = prow[(j + 0)  * 64];
        float p1 = prow[(j + 4)  * 64];
        float p2 = prow[(j + 8)  * 64];
        float p3 = prow[(j + 12) * 64];
        #pragma unroll
        for (int h = 0; h < 4; h++) {
            acc[h] += ps[h * 1024 + j]      * p0
                    + ps[h * 1024 + j + 4]  * p1
                    + ps[h * 1024 + j + 8]  * p2
                    + ps[h * 1024 + j + 12] * p3;
        }
    }
    #pragma unroll
    for (int h = 0; h < 4; h++) red[(g * 4 + h) * 64 + c] = acc[h];
    __syncthreads();
    {
        const int c2 = t & 63, h2 = t >> 6;
        float s = red[(0 * 4 + h2) * 64 + c2] + red[(1 * 4 + h2) * 64 + c2]
                + red[(2 * 4 + h2) * 64 + c2] + red[(3 * 4 + h2) * 64 + c2];
        g_opair[i * 256 + h2 * 64 + c2] = s;
    }
}

// ---------------------------------------------------------------------------
// kattnv: o_s = attn@V, o_pt_g = attn@Vg. grid=256 (64 i-tiles x 4 heads), blk=256
// ---------------------------------------------------------------------------
__global__ __launch_bounds__(256) void kattnv()
{
    __shared__ float As[16][129];
    __shared__ float Vs[128][45];

    const int h  = blockIdx.x & 3;
    const int i0 = (blockIdx.x >> 2) * 16;
    const int tid = threadIdx.x;
    const int r  = tid & 15;
    const int nb = tid >> 4;
    const int n2 = nb + 32;

    float acc0 = 0.f, acc1 = 0.f, acc2 = 0.f;

    for (int j0 = 0; j0 < 1024; j0 += 128) {
        __syncthreads();
        if (tid < 128) {
            int jj = tid;
            const float4* vp = (const float4*)(g_Vcat + (size_t)(j0 + jj) * 176 + h * 32);
            #pragma unroll
            for (int q = 0; q < 8; q++) {
                float4 v = vp[q];
                Vs[jj][q * 4 + 0] = v.x; Vs[jj][q * 4 + 1] = v.y;
                Vs[jj][q * 4 + 2] = v.z; Vs[jj][q * 4 + 3] = v.w;
            }
            const float4* gp = (const float4*)(g_Vcat + (size_t)(j0 + jj) * 176 + 128 + h * 12);
            #pragma unroll
            for (int q = 0; q < 3; q++) {
                float4 v = gp[q];
                Vs[jj][32 + q * 4 + 0] = v.x; Vs[jj][32 + q * 4 + 1] = v.y;
                Vs[jj][32 + q * 4 + 2] = v.z; Vs[jj][32 + q * 4 + 3] = v.w;
            }
        } else {
            int t2 = tid - 128;
            for (int u = t2; u < 2048; u += 128) {
                int rr = u >> 7, jj = u & 127;
                As[rr][jj] = g_attn[((size_t)h * 1024 + (i0 + rr)) * 1024 + j0 + jj];
            }
        }
        __syncthreads();
        #pragma unroll 8
        for (int jj = 0; jj < 128; jj++) {
            float a = As[r][jj];
            acc0 += a * Vs[jj][nb];
            acc1 += a * Vs[jj][nb + 16];
            acc2 += a * Vs[jj][n2];
        }
    }
    int i = i0 + r;
    g_os[i * 128 + h * 32 + nb]      = acc0;
    g_os[i * 128 + h * 32 + nb + 16] = acc1;
    if (n2 < 44) g_optg[i * 48 + h * 12 + (n2 - 32)] = acc2;
}

// ---------------------------------------------------------------------------
// kfinal: rotation+norm, concat, out = single + f@Wout + b_out.
// grid=256 (4 rows/block), blk=512 (k split in quarters)
// ---------------------------------------------------------------------------
__global__ __launch_bounds__(512) void kfinal(
    const float* __restrict__ single, const float* __restrict__ T,
    const float* __restrict__ Wout,   const float* __restrict__ b_out,
    float* __restrict__ out)
{
    __shared__ float fs[448 * 4];        // [k][r]
    __shared__ float part[4 * 4 * 128];  // [quarter][r][d]

    const int t  = threadIdx.x;
    const int i0 = blockIdx.x * 4;

    if (t < 512) {
        int r = t & 3, k = t >> 2;
        fs[k * 4 + r] = g_os[(i0 + r) * 128 + k];
    }
    for (int u = t; u < 1024; u += 512) {
        int r = u & 3, k2 = u >> 2;
        fs[(128 + k2) * 4 + r] = g_opair[(i0 + r) * 256 + k2];
    }
    if (t < 64) {
        int r = t >> 4, hp = t & 15, h = hp >> 2, p = hp & 3;
        int i = i0 + r;
        float Rm[3][3], tv[3];
        #pragma unroll
        for (int y = 0; y < 3; y++) {
            #pragma unroll
            for (int x = 0; x < 3; x++) Rm[y][x] = T[i * 16 + y * 4 + x];
            tv[y] = T[i * 16 + y * 4 + 3];
        }
        float g0 = g_optg[i * 48 + h * 12 + p * 3 + 0] - tv[0];
        float g1 = g_optg[i * 48 + h * 12 + p * 3 + 1] - tv[1];
        float g2 = g_optg[i * 48 + h * 12 + p * 3 + 2] - tv[2];
        float nrm = 0.f;
        #pragma unroll
        for (int x = 0; x < 3; x++) {
            float v = Rm[0][x] * g0 + Rm[1][x] * g1 + Rm[2][x] * g2;
            fs[(384 + h * 12 + p * 3 + x) * 4 + r] = v;
            nrm += v * v;
        }
        fs[(432 + h * 4 + p) * 4 + r] = sqrtf(nrm);
    }
    __syncthreads();

    const int d = t & 127, q = t >> 7;   // quarter 0..3
    float a0 = 0.f, a1 = 0.f, a2 = 0.f, a3 = 0.f;
    const int k0 = q * 112;
    #pragma unroll 8
    for (int k = k0; k < k0 + 112; k++) {
        float w = Wout[k * 128 + d];
        float4 f = *(const float4*)&fs[k * 4];
        a0 += f.x * w; a1 += f.y * w; a2 += f.z * w; a3 += f.w * w;
    }
    part[(q * 4 + 0) * 128 + d] = a0;
    part[(q * 4 + 1) * 128 + d] = a1;
    part[(q * 4 + 2) * 128 + d] = a2;
    part[(q * 4 + 3) * 128 + d] = a3;
    __syncthreads();

    {
        const int r = t >> 7, dd = t & 127;
        float s = part[(0 * 4 + r) * 128 + dd] + part[(1 * 4 + r) * 128 + dd]
                + part[(2 * 4 + r) * 128 + dd] + part[(3 * 4 + r) * 128 + dd];
        out[(i0 + r) * 128 + dd] = single[(i0 + r) * 128 + dd] + s + b_out[dd];
    }
}

// ---------------------------------------------------------------------------
extern "C" void kernel_launch(void* const* d_in, const int* in_sizes, int n_in,
                              void* d_out, int out_size)
{
    const float* single = (const float*)d_in[0];
    const float* pair   = (const float*)d_in[1];
    const float* T      = (const float*)d_in[2];
    const float* w_C    = (const float*)d_in[3];
    const float* ln_g   = (const float*)d_in[4];
    const float* ln_b   = (const float*)d_in[5];
    const float* Wq     = (const float*)d_in[6];
    const float* Wk     = (const float*)d_in[7];
    const float* Wv     = (const float*)d_in[8];
    const float* Wqpt   = (const float*)d_in[9];
    const float* Wkpt   = (const float*)d_in[10];
    const float* Wvpt   = (const float*)d_in[11];
    const float* Wb     = (const float*)d_in[12];
    const float* Wout   = (const float*)d_in[13];
    const float* b_out  = (const float*)d_in[14];
    float* out = (float*)d_out;

    static int smem_set = 0;
    const int klogits_smem = (16384 + 704 + 128 + 128) * 4;  // 69376 B
    if (!smem_set) {
        cudaFuncSetAttribute(klogits, cudaFuncAttributeMaxDynamicSharedMemorySize,
                             klogits_smem);
        smem_set = 1;
    }

    kprep<<<256, 256>>>(single, T, w_C, ln_g, ln_b, Wq, Wk, Wv, Wqpt, Wkpt, Wvpt);
    kbias<<<8192, 128>>>(pair, Wb);
    klogits<<<256, 256, klogits_smem>>>();
    kopair<<<1024, 256>>>(pair);
    kattnv<<<256, 256>>>();
    kfinal<<<256, 512>>>(single, T, Wout, b_out, out);
}